// round 12
// baseline (speedup 1.0000x reference)
#include <cuda_runtime.h>
#include <math.h>
#include <stdint.h>

#define K_COMP 8192
#define N_SAMP 8192
#define B_X    2048
#define D_W    13

#define LOG_2PI 1.8378770664093453f
#define L2E     1.4426950408889634f

#define NC    16                 // n-chunks (512 components each)
#define NB_PC 64                 // col-blocks (of 8 comps) per chunk

#define LSE_BLOCKS (NC * 64)            // 1024 (first: longest blocks)
#define REG_BLOCKS (N_SAMP / 8)         // 1024 (8 warps/block, 1 sample/warp)
#define RED_BLOCKS 64

// smem: lse phase-B needs 16KB (Bfrag) + 4KB (gu) = 20KB; phase-A (9.2KB) and
// reg xy (16KB) fit inside the same buffer. 20KB x 4 blocks/SM = 80KB (safe).
#define SMEM_BYTES (NB_PC * 32 * 8 + NB_PC * 4 * 16)

// ---------------- scratch (no allocations allowed) ----------------
__device__ float  g_wn[N_SAMP];           // ||w||^2 (written by reg blocks)
__device__ float  g_dsum[N_SAMP];         // sum_b (y_pred - y)^2
__device__ float  g_SP[NC][N_SAMP];       // per-chunk partial exp-sums
__device__ double g_part[RED_BLOCKS][3];  // per-block (q, wn, dsum) sums
__device__ unsigned g_ticket;             // last-block ticket (self-resetting)

__device__ __forceinline__ float tanh_fast(float x) {
    float r; asm("tanh.approx.f32 %0, %1;" : "=f"(r) : "f"(x)); return r;
}
__device__ __forceinline__ float exp2_fast(float x) {
    float r; asm("ex2.approx.f32 %0, %1;" : "=f"(r) : "f"(x)); return r;
}
// pack two f32 -> bf16x2, lo in low 16 bits
__device__ __forceinline__ unsigned packbf(float lo, float hi) {
    unsigned r; asm("cvt.rn.bf16x2.f32 %0, %1, %2;" : "=r"(r) : "f"(hi), "f"(lo)); return r;
}
__device__ __forceinline__ float softplus_f(float rho) {
    return (rho > 20.f) ? rho : log1pf(__expf(rho));
}

// ---------------- kernel 1: FUSED everything (self-staging) ----------------
// blocks [0, LSE_BLOCKS): stage w (phase A) + comps (phase B) in-block, then
//   tensor-core mma + exp2 sum.  chunk = bid>>6, grp = bid&63.
// blocks [LSE_BLOCKS, +REG_BLOCKS): self-gather w, regression, write wn+dsum.
__global__ __launch_bounds__(256, 4) void fused_all(const float* __restrict__ emp,
                                                    const float* __restrict__ rhos,
                                                    const float* __restrict__ eps,
                                                    const int* __restrict__ idxs,
                                                    const float* __restrict__ x,
                                                    const float* __restrict__ y) {
    __shared__ __align__(16) unsigned char smem_raw[SMEM_BYTES];   // 20KB

    int tid = threadIdx.x;
    int wid = tid >> 5, lane = tid & 31;

    if (blockIdx.x < LSE_BLOCKS) {
        int gid = lane >> 2, tg = lane & 3;
        int chunk = blockIdx.x >> 6;            // 0..15
        int grp   = blockIdx.x & 63;
        int rb = grp * 8 + wid;                 // row-block (16 samples)
        int s0 = rb * 16;
        int sBase = grp * 128;                  // block's 128 samples

        // ---- phase A: stage w for the block's 128 samples ----
        float* swf = (float*)smem_raw;                    // [128][17]
        float* sWN = (float*)(smem_raw + 128 * 17 * 4);   // [128]
        if (tid < 128) {
            int s = sBase + tid;
            int idx = __ldg(&idxs[s]);
            float sd = softplus_f(__ldg(&rhos[idx]));
            float wn = 0.f;
#pragma unroll
            for (int d = 0; d < D_W; d++) {
                float w = fmaf(__ldg(&eps[s * D_W + d]), sd, __ldg(&emp[idx * D_W + d]));
                swf[tid * 17 + d] = w;
                wn = fmaf(w, w, wn);
            }
            swf[tid * 17 + 13] = 0.f;
            swf[tid * 17 + 14] = 0.f;
            swf[tid * 17 + 15] = 0.f;
            sWN[tid] = wn;
        }
        __syncthreads();

        // A fragments (m16n8k16 row.col A layout) straight into registers
        int r0 = wid * 16 + gid;
        const float* w0 = &swf[r0 * 17];
        const float* w8 = &swf[(r0 + 8) * 17];
        int k0 = tg * 2;
        uint4 af;
        af.x = packbf(w0[k0],     w0[k0 + 1]);
        af.y = packbf(w8[k0],     w8[k0 + 1]);
        af.z = packbf(w0[k0 + 8], w0[k0 + 9]);
        af.w = packbf(w8[k0 + 8], w8[k0 + 9]);
        float hw0 = -0.5f * sWN[r0];
        float hw8 = -0.5f * sWN[r0 + 8];
        __syncthreads();

        // ---- phase B: stage this chunk's 512 comps (Bfrags + g,u) ----
        uint2*  sB  = (uint2*)smem_raw;                       // [NB_PC*32] 16KB
        float4* sGU = (float4*)(smem_raw + NB_PC * 32 * 8);   // [NB_PC*4]   4KB
        {
            int p = tid;                       // pair index 0..255
            int nbl = p >> 2, ptg = p & 3;
            int nbase = chunk * 512 + 2 * p;   // two consecutive comps
            float e[2][16];
            float gg[2], uu[2];
#pragma unroll
            for (int h = 0; h < 2; h++) {
                int n = nbase + h;
                float sd = softplus_f(__ldg(&rhos[n]));
                float var = sd * sd;
                float inv = 1.f / var;
                float en = 0.f;
#pragma unroll
                for (int d = 0; d < D_W; d++) {
                    float v = __ldg(&emp[n * D_W + d]);
                    e[h][d] = v;
                    en = fmaf(v, v, en);
                }
                e[h][13] = e[h][14] = e[h][15] = 0.f;
                float c = -0.5f * ((float)D_W * LOG_2PI + (float)D_W * __logf(var));
                gg[h] = L2E * inv;
                uu[h] = L2E * (c - 0.5f * inv * en);
            }
            sGU[nbl * 4 + ptg] = make_float4(gg[0], gg[1], uu[0], uu[1]);
#pragma unroll
            for (int h = 0; h < 2; h++) {
                int gc = (2 * p + h) & 7;      // comp's gid within its nb
#pragma unroll
                for (int t2 = 0; t2 < 4; t2++) {
                    int kk = 2 * t2;
                    uint2 v;
                    v.x = packbf(e[h][kk],     e[h][kk + 1]);
                    v.y = packbf(e[h][kk + 8], e[h][kk + 9]);
                    sB[nbl * 32 + gc * 4 + t2] = v;
                }
            }
        }
        __syncthreads();

        // ---- mainloop: mma + exp2 ----
        float S0 = 0.f, S8 = 0.f;
#pragma unroll 4
        for (int i = 0; i < NB_PC; i++) {
            uint2 bf = sB[i * 32 + lane];       // LDS.64, conflict-free
            float4 gu = sGU[i * 4 + tg];        // LDS.128, quad-broadcast
            float c0 = hw0, c1 = hw0, c2 = hw8, c3 = hw8;
            asm volatile(
                "mma.sync.aligned.m16n8k16.row.col.f32.bf16.bf16.f32 "
                "{%0,%1,%2,%3}, {%4,%5,%6,%7}, {%8,%9}, {%0,%1,%2,%3};"
                : "+f"(c0), "+f"(c1), "+f"(c2), "+f"(c3)
                : "r"(af.x), "r"(af.y), "r"(af.z), "r"(af.w),
                  "r"(bf.x), "r"(bf.y));
            // t = g*(dot - 0.5||w||^2) + u  (base-2, unshifted; always < 0)
            S0 += exp2_fast(fmaf(gu.x, c0, gu.z));
            S0 += exp2_fast(fmaf(gu.y, c1, gu.w));
            S8 += exp2_fast(fmaf(gu.x, c2, gu.z));
            S8 += exp2_fast(fmaf(gu.y, c3, gu.w));
        }

        S0 += __shfl_xor_sync(0xffffffffu, S0, 1);
        S0 += __shfl_xor_sync(0xffffffffu, S0, 2);
        S8 += __shfl_xor_sync(0xffffffffu, S8, 1);
        S8 += __shfl_xor_sync(0xffffffffu, S8, 2);
        if (tg == 0) {
            g_SP[chunk][s0 + gid]     = S0;
            g_SP[chunk][s0 + gid + 8] = S8;
        }
    } else {
        // ---- regression blocks: self-gather w, MLP over 2048 points ----
        float2* sxy = (float2*)smem_raw;        // [B_X] = 16KB
        int bid = blockIdx.x - LSE_BLOCKS;      // 0..1023
        for (int i = tid; i < B_X; i += 256)
            sxy[i] = make_float2(x[i], y[i]);
        __syncthreads();

        int s = bid * 8 + wid;
        int idx = __ldg(&idxs[s]);              // same addr all lanes: broadcast
        float sd = softplus_f(__ldg(&rhos[idx]));
        float wd = 0.f;
        if (lane < D_W)
            wd = fmaf(__ldg(&eps[s * D_W + lane]), sd, __ldg(&emp[idx * D_W + lane]));
        float wn = wd * wd;
#pragma unroll
        for (int o = 16; o; o >>= 1) wn += __shfl_xor_sync(0xffffffffu, wn, o);
        if (lane == 0) g_wn[s] = wn;            // sole writer of g_wn

        float p[D_W];
#pragma unroll
        for (int d = 0; d < D_W; d++) p[d] = __shfl_sync(0xffffffffu, wd, d);
        float w10 = p[0], w11 = p[1], b10 = p[2], b11 = p[3];
        float w200 = p[4], w201 = p[5], w210 = p[6], w211 = p[7];
        float b20 = p[8], b21 = p[9], w30 = p[10], w31 = p[11], b3 = p[12];

        float acc = 0.f;
#pragma unroll 8
        for (int t = 0; t < B_X / 32; t++) {
            float2 xy = sxy[t * 32 + lane];
            float h0 = tanh_fast(fmaf(w10, xy.x, b10));
            float h1 = tanh_fast(fmaf(w11, xy.x, b11));
            float z0 = tanh_fast(fmaf(w200, h0, fmaf(w201, h1, b20)));
            float z1 = tanh_fast(fmaf(w210, h0, fmaf(w211, h1, b21)));
            float yp = fmaf(w30, z0, fmaf(w31, z1, b3));
            float d = yp - xy.y;
            acc = fmaf(d, d, acc);
        }
#pragma unroll
        for (int o = 16; o; o >>= 1) acc += __shfl_xor_sync(0xffffffffu, acc, o);
        if (lane == 0) g_dsum[s] = acc;
    }
}

// ---------------- kernel 2: reduction + final (last-block pattern) ----------------
// 64 blocks x 128 thr; deterministic per-block double partials; last block
// combines in fixed index order, emits scalar, resets ticket (replay-safe).
__global__ __launch_bounds__(128) void reduce_final(float* __restrict__ out) {
    __shared__ double sh[3][4];
    int tid = threadIdx.x;
    int s = blockIdx.x * 128 + tid;

    float S = 0.f;
#pragma unroll
    for (int c = 0; c < NC; c++) S += g_SP[c][s];
    double q  = (double)__logf(S);
    double wn = (double)g_wn[s];
    double ds = (double)g_dsum[s];

    int lane = tid & 31, warp = tid >> 5;
#pragma unroll
    for (int o = 16; o; o >>= 1) {
        q  += __shfl_xor_sync(0xffffffffu, q, o);
        wn += __shfl_xor_sync(0xffffffffu, wn, o);
        ds += __shfl_xor_sync(0xffffffffu, ds, o);
    }
    if (lane == 0) { sh[0][warp] = q; sh[1][warp] = wn; sh[2][warp] = ds; }
    __syncthreads();

    __shared__ int s_last;
    if (tid == 0) {
        double bq = 0.0, bwn = 0.0, bds = 0.0;
#pragma unroll
        for (int i = 0; i < 4; i++) { bq += sh[0][i]; bwn += sh[1][i]; bds += sh[2][i]; }
        g_part[blockIdx.x][0] = bq;
        g_part[blockIdx.x][1] = bwn;
        g_part[blockIdx.x][2] = bds;
        __threadfence();
        unsigned t = atomicAdd(&g_ticket, 1u);
        s_last = (t == RED_BLOCKS - 1) ? 1 : 0;
    }
    __syncthreads();

    if (s_last && tid == 0) {
        double tq = 0.0, twn = 0.0, tds = 0.0;
#pragma unroll
        for (int i = 0; i < RED_BLOCKS; i++) {   // fixed order -> deterministic
            tq  += g_part[i][0];
            twn += g_part[i][1];
            tds += g_part[i][2];
        }
        const double LOG_2PI_D = 1.837877066409345483560659472811;
        double mean_q  = tq / (double)N_SAMP - log((double)K_COMP);
        double mean_wn = twn / (double)N_SAMP;
        double mean_d  = tds / (double)N_SAMP;
        double data_lp = -0.5 * 5.0 * mean_d
                       + (double)B_X * 0.5 * (log(5.0) - LOG_2PI_D);
        double prior   = -0.5 * mean_wn - 0.5 * (double)D_W * LOG_2PI_D;
        double kl      = mean_q - prior;
        out[0] = (float)(data_lp - kl);
        g_ticket = 0;                            // reset for next graph replay
    }
}

// ---------------- launch ----------------
extern "C" void kernel_launch(void* const* d_in, const int* in_sizes, int n_in,
                              void* d_out, int out_size) {
    const float* emp  = (const float*)d_in[0];
    const float* rhos = (const float*)d_in[1];
    const float* x    = (const float*)d_in[2];
    const float* y    = (const float*)d_in[3];
    const float* eps  = (const float*)d_in[4];
    const int*   idxs = (const int*)d_in[5];
    float* out = (float*)d_out;

    fused_all<<<LSE_BLOCKS + REG_BLOCKS, 256>>>(emp, rhos, eps, idxs, x, y);
    reduce_final<<<RED_BLOCKS, 128>>>(out);
}

// round 13
// speedup vs baseline: 1.0797x; 1.0797x over previous
#include <cuda_runtime.h>
#include <math.h>
#include <stdint.h>

#define K_COMP 8192
#define N_SAMP 8192
#define B_X    2048
#define D_W    13

#define LOG_2PI 1.8378770664093453f
#define L2E     1.4426950408889634f

#define NC    16                 // n-chunks (512 components each)
#define NB_PC 64                 // col-blocks (of 8 comps) per chunk
#define NRB   (N_SAMP / 16)      // 512 row-blocks

#define LSE_BLOCKS (NC * 64)            // 1024 (first: longest blocks)
#define REG_BLOCKS (N_SAMP / 8)         // 1024 (8 warps/block, 1 sample/warp)
#define RED_BLOCKS 32

// smem: lse needs 16KB (Bfrag) + 4KB (gu) = 20KB; reg xy 16KB fits inside.
// 20KB x 4 blocks/SM = 80KB (within default carveout; 40KB version regressed).
#define SMEM_BYTES (NB_PC * 32 * 8 + NB_PC * 4 * 16)

// ---------------- scratch (no allocations allowed) ----------------
__device__ float  g_wn[N_SAMP];           // ||w||^2 (written by prep_samp ONLY)
__device__ uint4  g_Afrag[NRB * 32];      // per-lane A fragments (bf16x2 x4)
__device__ float  g_dsum[N_SAMP];         // sum_b (y_pred - y)^2
__device__ float  g_SP[NC][N_SAMP];       // per-chunk partial exp-sums
__device__ double g_part[RED_BLOCKS][3];  // per-block (q, wn, dsum) sums
__device__ unsigned g_ticket;             // last-block ticket (self-resetting)

__device__ __forceinline__ float tanh_fast(float x) {
    float r; asm("tanh.approx.f32 %0, %1;" : "=f"(r) : "f"(x)); return r;
}
__device__ __forceinline__ float exp2_fast(float x) {
    float r; asm("ex2.approx.f32 %0, %1;" : "=f"(r) : "f"(x)); return r;
}
// pack two f32 -> bf16x2, lo in low 16 bits
__device__ __forceinline__ unsigned packbf(float lo, float hi) {
    unsigned r; asm("cvt.rn.bf16x2.f32 %0, %1, %2;" : "=r"(r) : "f"(hi), "f"(lo)); return r;
}
__device__ __forceinline__ float softplus_f(float rho) {
    return (rho > 20.f) ? rho : log1pf(__expf(rho));
}

// ---------------- kernel 1: sample prep, half-warp per sample ----------------
// 512 blocks x 256 thr; each 16-lane half-warp gathers one sample's 13 dims in
// PARALLEL (vs 13 serial gathers per thread before -> 16x the memory-level
// parallelism). Writes g_Afrag (mma A layout) + g_wn.
__global__ __launch_bounds__(256) void prep_samp(const float* __restrict__ emp,
                                                 const float* __restrict__ rhos,
                                                 const float* __restrict__ eps,
                                                 const int* __restrict__ idxs) {
    __shared__ float sw[16][17];
    int tid = threadIdx.x;
    int wid = tid >> 5, lane = tid & 31;
    int half = lane >> 4, d = lane & 15;
    int ls = wid * 2 + half;               // local sample 0..15
    int s = blockIdx.x * 16 + ls;

    int idx = __ldg(&idxs[s]);
    float sd = softplus_f(__ldg(&rhos[idx]));
    float w = 0.f;
    if (d < D_W)
        w = fmaf(__ldg(&eps[s * D_W + d]), sd, __ldg(&emp[idx * D_W + d]));
    float wn = w * w;
#pragma unroll
    for (int o = 8; o; o >>= 1) wn += __shfl_xor_sync(0xffffffffu, wn, o); // within half
    if (d == 0) g_wn[s] = wn;
    sw[ls][d] = w;                         // d=13..15 lanes store 0 (padding)
    __syncthreads();

    if (tid < 32) {                        // A frags for this row-block
        int gid = tid >> 2, tg = tid & 3, k0 = tg * 2;
        uint4 af;
        af.x = packbf(sw[gid][k0],         sw[gid][k0 + 1]);
        af.y = packbf(sw[gid + 8][k0],     sw[gid + 8][k0 + 1]);
        af.z = packbf(sw[gid][k0 + 8],     sw[gid][k0 + 9]);
        af.w = packbf(sw[gid + 8][k0 + 8], sw[gid + 8][k0 + 9]);
        g_Afrag[blockIdx.x * 32 + tid] = af;
    }
}

// ---------------- kernel 2: FUSED tensor-core lse + regression ----------------
// blocks [0, LSE_BLOCKS): stage this chunk's 512 comps (B-frags + g,u) in
//   smem (ONE sync), then mma + exp2 sum; A-frags/wn come from prep_samp.
// blocks [LSE_BLOCKS, +REG_BLOCKS): self-gather w, regression, write dsum.
__global__ __launch_bounds__(256, 4) void fused_all(const float* __restrict__ emp,
                                                    const float* __restrict__ rhos,
                                                    const float* __restrict__ eps,
                                                    const int* __restrict__ idxs,
                                                    const float* __restrict__ x,
                                                    const float* __restrict__ y) {
    __shared__ __align__(16) unsigned char smem_raw[SMEM_BYTES];   // 20KB

    int tid = threadIdx.x;
    int wid = tid >> 5, lane = tid & 31;

    if (blockIdx.x < LSE_BLOCKS) {
        int gid = lane >> 2, tg = lane & 3;
        int chunk = blockIdx.x >> 6;            // 0..15
        int grp   = blockIdx.x & 63;
        int rb = grp * 8 + wid;                 // row-block (16 samples)
        int s0 = rb * 16;

        uint2*  sB  = (uint2*)smem_raw;                       // [NB_PC*32] 16KB
        float4* sGU = (float4*)(smem_raw + NB_PC * 32 * 8);   // [NB_PC*4]   4KB

        // stage this chunk's comps: thread p handles comp pair (2p, 2p+1)
        {
            int p = tid;
            int nbl = p >> 2, ptg = p & 3;
            int nbase = chunk * 512 + 2 * p;
            float gg[2], uu[2];
#pragma unroll
            for (int h = 0; h < 2; h++) {
                int n = nbase + h;
                float sd = softplus_f(__ldg(&rhos[n]));
                float var = sd * sd;
                float inv = 1.f / var;
                float e[16];
                float en = 0.f;
#pragma unroll
                for (int dd = 0; dd < D_W; dd++) {
                    float v = __ldg(&emp[n * D_W + dd]);
                    e[dd] = v;
                    en = fmaf(v, v, en);
                }
                e[13] = e[14] = e[15] = 0.f;
                float c = -0.5f * ((float)D_W * LOG_2PI + (float)D_W * __logf(var));
                gg[h] = L2E * inv;
                uu[h] = L2E * (c - 0.5f * inv * en);
                int gc = (2 * p + h) & 7;      // comp's gid within its nb
#pragma unroll
                for (int t2 = 0; t2 < 4; t2++) {
                    int kk = 2 * t2;
                    uint2 v;
                    v.x = packbf(e[kk],     e[kk + 1]);
                    v.y = packbf(e[kk + 8], e[kk + 9]);
                    sB[nbl * 32 + gc * 4 + t2] = v;
                }
            }
            sGU[nbl * 4 + ptg] = make_float4(gg[0], gg[1], uu[0], uu[1]);
        }

        // A frags + norms from prep (global; no smem conflict with staging)
        uint4 af = g_Afrag[rb * 32 + lane];
        float hw0 = -0.5f * __ldg(&g_wn[s0 + gid]);
        float hw8 = -0.5f * __ldg(&g_wn[s0 + gid + 8]);
        float S0 = 0.f, S8 = 0.f;
        __syncthreads();                       // the ONLY sync in this branch

#pragma unroll 4
        for (int i = 0; i < NB_PC; i++) {
            uint2 bf = sB[i * 32 + lane];       // LDS.64, conflict-free
            float4 gu = sGU[i * 4 + tg];        // LDS.128, quad-broadcast
            float c0 = hw0, c1 = hw0, c2 = hw8, c3 = hw8;
            asm volatile(
                "mma.sync.aligned.m16n8k16.row.col.f32.bf16.bf16.f32 "
                "{%0,%1,%2,%3}, {%4,%5,%6,%7}, {%8,%9}, {%0,%1,%2,%3};"
                : "+f"(c0), "+f"(c1), "+f"(c2), "+f"(c3)
                : "r"(af.x), "r"(af.y), "r"(af.z), "r"(af.w),
                  "r"(bf.x), "r"(bf.y));
            // t = g*(dot - 0.5||w||^2) + u  (base-2, unshifted; always < 0)
            S0 += exp2_fast(fmaf(gu.x, c0, gu.z));
            S0 += exp2_fast(fmaf(gu.y, c1, gu.w));
            S8 += exp2_fast(fmaf(gu.x, c2, gu.z));
            S8 += exp2_fast(fmaf(gu.y, c3, gu.w));
        }

        S0 += __shfl_xor_sync(0xffffffffu, S0, 1);
        S0 += __shfl_xor_sync(0xffffffffu, S0, 2);
        S8 += __shfl_xor_sync(0xffffffffu, S8, 1);
        S8 += __shfl_xor_sync(0xffffffffu, S8, 2);
        if (tg == 0) {
            g_SP[chunk][s0 + gid]     = S0;
            g_SP[chunk][s0 + gid + 8] = S8;
        }
    } else {
        // ---- regression blocks: self-gather w, MLP over 2048 points ----
        float2* sxy = (float2*)smem_raw;        // [B_X] = 16KB
        int bid = blockIdx.x - LSE_BLOCKS;      // 0..1023
        for (int i = tid; i < B_X; i += 256)
            sxy[i] = make_float2(x[i], y[i]);
        __syncthreads();

        int s = bid * 8 + wid;
        int idx = __ldg(&idxs[s]);              // same addr all lanes: broadcast
        float sd = softplus_f(__ldg(&rhos[idx]));
        float wd = 0.f;
        if (lane < D_W)
            wd = fmaf(__ldg(&eps[s * D_W + lane]), sd, __ldg(&emp[idx * D_W + lane]));

        float p[D_W];
#pragma unroll
        for (int d = 0; d < D_W; d++) p[d] = __shfl_sync(0xffffffffu, wd, d);
        float w10 = p[0], w11 = p[1], b10 = p[2], b11 = p[3];
        float w200 = p[4], w201 = p[5], w210 = p[6], w211 = p[7];
        float b20 = p[8], b21 = p[9], w30 = p[10], w31 = p[11], b3 = p[12];

        float acc = 0.f;
#pragma unroll 8
        for (int t = 0; t < B_X / 32; t++) {
            float2 xy = sxy[t * 32 + lane];
            float h0 = tanh_fast(fmaf(w10, xy.x, b10));
            float h1 = tanh_fast(fmaf(w11, xy.x, b11));
            float z0 = tanh_fast(fmaf(w200, h0, fmaf(w201, h1, b20)));
            float z1 = tanh_fast(fmaf(w210, h0, fmaf(w211, h1, b21)));
            float yp = fmaf(w30, z0, fmaf(w31, z1, b3));
            float d = yp - xy.y;
            acc = fmaf(d, d, acc);
        }
#pragma unroll
        for (int o = 16; o; o >>= 1) acc += __shfl_xor_sync(0xffffffffu, acc, o);
        if (lane == 0) g_dsum[s] = acc;
    }
}

// ---------------- kernel 3: reduction + final (last-block pattern) ----------------
// 32 blocks x 256 thr (the 64x128 variant regressed badly — reverted).
__global__ __launch_bounds__(256) void reduce_final(float* __restrict__ out) {
    __shared__ double sh[3][8];
    int tid = threadIdx.x;
    int s = blockIdx.x * 256 + tid;

    float S = 0.f;
#pragma unroll
    for (int c = 0; c < NC; c++) S += g_SP[c][s];
    double q  = (double)__logf(S);
    double wn = (double)g_wn[s];
    double ds = (double)g_dsum[s];

    int lane = tid & 31, warp = tid >> 5;
#pragma unroll
    for (int o = 16; o; o >>= 1) {
        q  += __shfl_xor_sync(0xffffffffu, q, o);
        wn += __shfl_xor_sync(0xffffffffu, wn, o);
        ds += __shfl_xor_sync(0xffffffffu, ds, o);
    }
    if (lane == 0) { sh[0][warp] = q; sh[1][warp] = wn; sh[2][warp] = ds; }
    __syncthreads();

    __shared__ int s_last;
    if (tid == 0) {
        double bq = 0.0, bwn = 0.0, bds = 0.0;
#pragma unroll
        for (int i = 0; i < 8; i++) { bq += sh[0][i]; bwn += sh[1][i]; bds += sh[2][i]; }
        g_part[blockIdx.x][0] = bq;
        g_part[blockIdx.x][1] = bwn;
        g_part[blockIdx.x][2] = bds;
        __threadfence();
        unsigned t = atomicAdd(&g_ticket, 1u);
        s_last = (t == RED_BLOCKS - 1) ? 1 : 0;
    }
    __syncthreads();

    if (s_last && tid == 0) {
        double tq = 0.0, twn = 0.0, tds = 0.0;
#pragma unroll
        for (int i = 0; i < RED_BLOCKS; i++) {   // fixed order -> deterministic
            tq  += g_part[i][0];
            twn += g_part[i][1];
            tds += g_part[i][2];
        }
        const double LOG_2PI_D = 1.837877066409345483560659472811;
        double mean_q  = tq / (double)N_SAMP - log((double)K_COMP);
        double mean_wn = twn / (double)N_SAMP;
        double mean_d  = tds / (double)N_SAMP;
        double data_lp = -0.5 * 5.0 * mean_d
                       + (double)B_X * 0.5 * (log(5.0) - LOG_2PI_D);
        double prior   = -0.5 * mean_wn - 0.5 * (double)D_W * LOG_2PI_D;
        double kl      = mean_q - prior;
        out[0] = (float)(data_lp - kl);
        g_ticket = 0;                            // reset for next graph replay
    }
}

// ---------------- launch ----------------
extern "C" void kernel_launch(void* const* d_in, const int* in_sizes, int n_in,
                              void* d_out, int out_size) {
    const float* emp  = (const float*)d_in[0];
    const float* rhos = (const float*)d_in[1];
    const float* x    = (const float*)d_in[2];
    const float* y    = (const float*)d_in[3];
    const float* eps  = (const float*)d_in[4];
    const int*   idxs = (const int*)d_in[5];
    float* out = (float*)d_out;

    prep_samp<<<NRB, 256>>>(emp, rhos, eps, idxs);
    fused_all<<<LSE_BLOCKS + REG_BLOCKS, 256>>>(emp, rhos, eps, idxs, x, y);
    reduce_final<<<RED_BLOCKS, 256>>>(out);
}

// round 14
// speedup vs baseline: 1.1904x; 1.1026x over previous
#include <cuda_runtime.h>
#include <math.h>
#include <stdint.h>

#define K_COMP 8192
#define N_SAMP 8192
#define B_X    2048
#define D_W    13

#define LOG_2PI 1.8378770664093453f
#define L2E     1.4426950408889634f

#define NC    16                 // n-chunks (512 components each)
#define NB_PC 64                 // col-blocks (of 8 comps) per chunk
#define NNB   (K_COMP / 8)       // 1024 col-blocks total
#define NRB   (N_SAMP / 16)      // 512 row-blocks

#define PREP_BLOCKS NRB                 // 512  (bids [0,512): no deps)
#define REG_BLOCKS  (N_SAMP / 8)        // 1024 (bids [512,1536): no deps)
#define LSE_BLOCKS  (NC * 64)           // 1024 (bids [1536,2560): wait on prep)
#define RED_BLOCKS  32

// smem: lse needs 16KB (Bfrag) + 4KB (gu) = 20KB; reg xy 16KB and prep tiny
// buffers fit inside. 20KB x 4 blocks/SM = 80KB (within default carveout).
#define SMEM_BYTES (NB_PC * 32 * 8 + NB_PC * 4 * 16)

// ---------------- scratch (no allocations allowed) ----------------
__device__ float  g_wn[N_SAMP];           // ||w||^2 (written by prep blocks)
__device__ uint4  g_Afrag[NRB * 32];      // per-lane A fragments (bf16x2 x4)
__device__ float4 g_gu[K_COMP / 2];       // (g0,g1,u0,u1) per col-pair
__device__ uint2  g_Bfrag[NNB * 32];      // per-lane B fragments (bf16x2 x2)
__device__ float  g_dsum[N_SAMP];         // sum_b (y_pred - y)^2
__device__ float  g_SP[NC][N_SAMP];       // per-chunk partial exp-sums
__device__ double g_part[RED_BLOCKS][3];  // per-block (q, wn, dsum) sums
__device__ unsigned g_ticket;             // reduce last-block ticket
__device__ unsigned g_prep_done;          // prep completion counter

__device__ __forceinline__ float tanh_fast(float x) {
    float r; asm("tanh.approx.f32 %0, %1;" : "=f"(r) : "f"(x)); return r;
}
__device__ __forceinline__ float exp2_fast(float x) {
    float r; asm("ex2.approx.f32 %0, %1;" : "=f"(r) : "f"(x)); return r;
}
// pack two f32 -> bf16x2, lo in low 16 bits
__device__ __forceinline__ unsigned packbf(float lo, float hi) {
    unsigned r; asm("cvt.rn.bf16x2.f32 %0, %1, %2;" : "=r"(r) : "f"(hi), "f"(lo)); return r;
}
__device__ __forceinline__ float softplus_f(float rho) {
    return (rho > 20.f) ? rho : log1pf(__expf(rho));
}

// ---------------- kernel 1: MEGA (prep + reg + lse, flag-gated) ----------------
// bids [0, PREP): sample prep (half-warp/sample) + 1/512 slice of comp prep.
//   All prep blocks are wave-1 resident (512 < ~592 slots) -> finish first.
// bids [PREP, PREP+REG): regression, no dependency (self-gathers w).
// bids [PREP+REG, ...): lse; spins (tid0+nanosleep) until prep counter hits
//   NRB. Dispatched last -> in practice never actually waits. Deadlock-free:
//   prep blocks are co-resident before any lse block starts.
__global__ __launch_bounds__(256, 4) void mega(const float* __restrict__ emp,
                                               const float* __restrict__ rhos,
                                               const float* __restrict__ eps,
                                               const int* __restrict__ idxs,
                                               const float* __restrict__ x,
                                               const float* __restrict__ y) {
    __shared__ __align__(16) unsigned char smem_raw[SMEM_BYTES];   // 20KB

    int tid = threadIdx.x;
    int wid = tid >> 5, lane = tid & 31;

    if (blockIdx.x < PREP_BLOCKS) {
        // ---- prep block: 16 samples (half-warp each) + comp-prep slice ----
        float (*sw)[17] = (float(*)[17])smem_raw;   // [16][17]
        int half = lane >> 4, d = lane & 15;
        int ls = wid * 2 + half;               // local sample 0..15
        int s = blockIdx.x * 16 + ls;

        int idx = __ldg(&idxs[s]);
        float sd = softplus_f(__ldg(&rhos[idx]));
        float w = 0.f;
        if (d < D_W)
            w = fmaf(__ldg(&eps[s * D_W + d]), sd, __ldg(&emp[idx * D_W + d]));
        float wn = w * w;
#pragma unroll
        for (int o = 8; o; o >>= 1) wn += __shfl_xor_sync(0xffffffffu, wn, o);
        if (d == 0) g_wn[s] = wn;
        sw[ls][d] = w;                         // d=13..15 store 0 (padding)

        // comp prep slice: flat thread id over 512*256 = 131072 threads
        int gidx = blockIdx.x * 256 + tid;
        if (gidx < K_COMP) {
            int k = gidx;
            float sdk = softplus_f(__ldg(&rhos[k]));
            float var = sdk * sdk;
            float inv = 1.f / var;
            float en = 0.f;
#pragma unroll
            for (int dd = 0; dd < D_W; dd++) {
                float v = __ldg(&emp[k * D_W + dd]);
                en = fmaf(v, v, en);
            }
            float c = -0.5f * ((float)D_W * LOG_2PI + (float)D_W * __logf(var));
            float* gu = (float*)&g_gu[k >> 1];
            gu[(k & 1) + 0] = L2E * inv;
            gu[(k & 1) + 2] = L2E * (c - 0.5f * inv * en);
        } else if (gidx < K_COMP + NNB * 32) {
            int t2 = gidx - K_COMP;
            int bl = t2 & 31, bgid = bl >> 2, btg = bl & 3;
            int nb = t2 >> 5;
            int n = nb * 8 + bgid;
            int k0 = btg * 2;
            float e0 = __ldg(&emp[n * D_W + k0]);
            float e1 = __ldg(&emp[n * D_W + k0 + 1]);
            float e2 = (k0 + 8 < D_W) ? __ldg(&emp[n * D_W + k0 + 8]) : 0.f;
            float e3 = (k0 + 9 < D_W) ? __ldg(&emp[n * D_W + k0 + 9]) : 0.f;
            uint2 r;
            r.x = packbf(e0, e1);
            r.y = packbf(e2, e3);
            g_Bfrag[t2] = r;
        }
        __syncthreads();

        if (tid < 32) {                        // A frags for this row-block
            int agid = tid >> 2, atg = tid & 3, k0 = atg * 2;
            uint4 af;
            af.x = packbf(sw[agid][k0],         sw[agid][k0 + 1]);
            af.y = packbf(sw[agid + 8][k0],     sw[agid + 8][k0 + 1]);
            af.z = packbf(sw[agid][k0 + 8],     sw[agid][k0 + 9]);
            af.w = packbf(sw[agid + 8][k0 + 8], sw[agid + 8][k0 + 9]);
            g_Afrag[blockIdx.x * 32 + tid] = af;
        }
        __syncthreads();
        if (tid == 0) {
            __threadfence();
            atomicAdd(&g_prep_done, 1u);
        }
    } else if (blockIdx.x < PREP_BLOCKS + REG_BLOCKS) {
        // ---- regression: self-gather w, MLP over 2048 points ----
        float2* sxy = (float2*)smem_raw;        // [B_X] = 16KB
        int bid = blockIdx.x - PREP_BLOCKS;     // 0..1023
        for (int i = tid; i < B_X; i += 256)
            sxy[i] = make_float2(x[i], y[i]);
        __syncthreads();

        int s = bid * 8 + wid;
        int idx = __ldg(&idxs[s]);              // same addr all lanes: broadcast
        float sd = softplus_f(__ldg(&rhos[idx]));
        float wd = 0.f;
        if (lane < D_W)
            wd = fmaf(__ldg(&eps[s * D_W + lane]), sd, __ldg(&emp[idx * D_W + lane]));

        float p[D_W];
#pragma unroll
        for (int d = 0; d < D_W; d++) p[d] = __shfl_sync(0xffffffffu, wd, d);
        float w10 = p[0], w11 = p[1], b10 = p[2], b11 = p[3];
        float w200 = p[4], w201 = p[5], w210 = p[6], w211 = p[7];
        float b20 = p[8], b21 = p[9], w30 = p[10], w31 = p[11], b3 = p[12];

        float acc = 0.f;
#pragma unroll 8
        for (int t = 0; t < B_X / 32; t++) {
            float2 xy = sxy[t * 32 + lane];
            float h0 = tanh_fast(fmaf(w10, xy.x, b10));
            float h1 = tanh_fast(fmaf(w11, xy.x, b11));
            float z0 = tanh_fast(fmaf(w200, h0, fmaf(w201, h1, b20)));
            float z1 = tanh_fast(fmaf(w210, h0, fmaf(w211, h1, b21)));
            float yp = fmaf(w30, z0, fmaf(w31, z1, b3));
            float d = yp - xy.y;
            acc = fmaf(d, d, acc);
        }
#pragma unroll
        for (int o = 16; o; o >>= 1) acc += __shfl_xor_sync(0xffffffffu, acc, o);
        if (lane == 0) g_dsum[s] = acc;
    } else {
        // ---- lse: wait for prep, stage chunk, mma + exp2 ----
        int lbid = blockIdx.x - PREP_BLOCKS - REG_BLOCKS;  // 0..1023
        int gid = lane >> 2, tg = lane & 3;
        int chunk = lbid >> 6;                  // 0..15
        int grp   = lbid & 63;
        int rb = grp * 8 + wid;                 // row-block (16 samples)
        int s0 = rb * 16;
        int nb0 = chunk * NB_PC;

        if (tid == 0) {
            while (atomicAdd(&g_prep_done, 0u) < (unsigned)NRB) __nanosleep(200);
            __threadfence();
        }
        __syncthreads();

        uint2*  sB  = (uint2*)smem_raw;                       // [NB_PC*32] 16KB
        float4* sGU = (float4*)(smem_raw + NB_PC * 32 * 8);   // [NB_PC*4]   4KB
        for (int i = tid; i < NB_PC * 32; i += 256) sB[i] = g_Bfrag[nb0 * 32 + i];
        if (tid < NB_PC * 4) sGU[tid] = g_gu[nb0 * 4 + tid];

        uint4 af = g_Afrag[rb * 32 + lane];
        float hw0 = -0.5f * __ldg(&g_wn[s0 + gid]);
        float hw8 = -0.5f * __ldg(&g_wn[s0 + gid + 8]);
        float S0 = 0.f, S8 = 0.f;
        __syncthreads();

#pragma unroll 4
        for (int i = 0; i < NB_PC; i++) {
            uint2 bf = sB[i * 32 + lane];       // LDS.64, conflict-free
            float4 gu = sGU[i * 4 + tg];        // LDS.128, quad-broadcast
            float c0 = hw0, c1 = hw0, c2 = hw8, c3 = hw8;
            asm volatile(
                "mma.sync.aligned.m16n8k16.row.col.f32.bf16.bf16.f32 "
                "{%0,%1,%2,%3}, {%4,%5,%6,%7}, {%8,%9}, {%0,%1,%2,%3};"
                : "+f"(c0), "+f"(c1), "+f"(c2), "+f"(c3)
                : "r"(af.x), "r"(af.y), "r"(af.z), "r"(af.w),
                  "r"(bf.x), "r"(bf.y));
            // t = g*(dot - 0.5||w||^2) + u  (base-2, unshifted; always < 0)
            S0 += exp2_fast(fmaf(gu.x, c0, gu.z));
            S0 += exp2_fast(fmaf(gu.y, c1, gu.w));
            S8 += exp2_fast(fmaf(gu.x, c2, gu.z));
            S8 += exp2_fast(fmaf(gu.y, c3, gu.w));
        }

        S0 += __shfl_xor_sync(0xffffffffu, S0, 1);
        S0 += __shfl_xor_sync(0xffffffffu, S0, 2);
        S8 += __shfl_xor_sync(0xffffffffu, S8, 1);
        S8 += __shfl_xor_sync(0xffffffffu, S8, 2);
        if (tg == 0) {
            g_SP[chunk][s0 + gid]     = S0;
            g_SP[chunk][s0 + gid + 8] = S8;
        }
    }
}

// ---------------- kernel 2: reduction + final (last-block pattern) ----------------
__global__ __launch_bounds__(256) void reduce_final(float* __restrict__ out) {
    __shared__ double sh[3][8];
    int tid = threadIdx.x;
    int s = blockIdx.x * 256 + tid;

    float S = 0.f;
#pragma unroll
    for (int c = 0; c < NC; c++) S += g_SP[c][s];
    double q  = (double)__logf(S);
    double wn = (double)g_wn[s];
    double ds = (double)g_dsum[s];

    int lane = tid & 31, warp = tid >> 5;
#pragma unroll
    for (int o = 16; o; o >>= 1) {
        q  += __shfl_xor_sync(0xffffffffu, q, o);
        wn += __shfl_xor_sync(0xffffffffu, wn, o);
        ds += __shfl_xor_sync(0xffffffffu, ds, o);
    }
    if (lane == 0) { sh[0][warp] = q; sh[1][warp] = wn; sh[2][warp] = ds; }
    __syncthreads();

    __shared__ int s_last;
    if (tid == 0) {
        double bq = 0.0, bwn = 0.0, bds = 0.0;
#pragma unroll
        for (int i = 0; i < 8; i++) { bq += sh[0][i]; bwn += sh[1][i]; bds += sh[2][i]; }
        g_part[blockIdx.x][0] = bq;
        g_part[blockIdx.x][1] = bwn;
        g_part[blockIdx.x][2] = bds;
        __threadfence();
        unsigned t = atomicAdd(&g_ticket, 1u);
        s_last = (t == RED_BLOCKS - 1) ? 1 : 0;
    }
    __syncthreads();

    if (s_last && tid == 0) {
        double tq = 0.0, twn = 0.0, tds = 0.0;
#pragma unroll
        for (int i = 0; i < RED_BLOCKS; i++) {   // fixed order -> deterministic
            tq  += g_part[i][0];
            twn += g_part[i][1];
            tds += g_part[i][2];
        }
        const double LOG_2PI_D = 1.837877066409345483560659472811;
        double mean_q  = tq / (double)N_SAMP - log((double)K_COMP);
        double mean_wn = twn / (double)N_SAMP;
        double mean_d  = tds / (double)N_SAMP;
        double data_lp = -0.5 * 5.0 * mean_d
                       + (double)B_X * 0.5 * (log(5.0) - LOG_2PI_D);
        double prior   = -0.5 * mean_wn - 0.5 * (double)D_W * LOG_2PI_D;
        double kl      = mean_q - prior;
        out[0] = (float)(data_lp - kl);
        g_ticket = 0;                            // reset for next graph replay
        g_prep_done = 0;                         // reset prep gate too
    }
}

// ---------------- launch ----------------
extern "C" void kernel_launch(void* const* d_in, const int* in_sizes, int n_in,
                              void* d_out, int out_size) {
    const float* emp  = (const float*)d_in[0];
    const float* rhos = (const float*)d_in[1];
    const float* x    = (const float*)d_in[2];
    const float* y    = (const float*)d_in[3];
    const float* eps  = (const float*)d_in[4];
    const int*   idxs = (const int*)d_in[5];
    float* out = (float*)d_out;

    mega<<<PREP_BLOCKS + REG_BLOCKS + LSE_BLOCKS, 256>>>(emp, rhos, eps, idxs, x, y);
    reduce_final<<<RED_BLOCKS, 256>>>(out);
}